// round 9
// baseline (speedup 1.0000x reference)
#include <cuda_runtime.h>
#include <cstdint>

#define T_STEPS 16
#define BATCH   32768
#define M_CTA   256
#define NBLK    (BATCH / M_CTA)   // 128 CTAs (single wave)
#define NTHR    512               // 16 warps

#define SMEM_BYTES 65536u

// weights transposed + quartered: [L][q][i][o'] = w[(q*64+o')][i]
__device__ float g_w23t[2][4][256][64];
__device__ float g_w4t[256][16];
// spike bit planes: [buf][cta][t][wd(8)][row(256)]
__device__ uint32_t g_bits[2u * NBLK * T_STEPS * 8u * 256u];
#define GB(b,cta,t,wd,r) (((((b)*NBLK + (cta))*T_STEPS + (t))*8u + (wd))*256u + (r))

__global__ void prep_kernel(const float* __restrict__ w2, const float* __restrict__ w3,
                            const float* __restrict__ w4) {
    int idx = blockIdx.x * 256 + threadIdx.x;      // grid 512 -> 0..131071
    int L = idx >> 16;
    int o = (idx >> 8) & 255;
    int i = idx & 255;
    g_w23t[L][o >> 6][i][o & 63] = (L ? w3 : w2)[o * 256 + i];
    if (idx < 4096) {
        int ii = idx >> 4, oo = idx & 15;
        g_w4t[ii][oo] = w4[oo * 256 + ii];
    }
}

// ---- packed f32x2 helpers ----
__device__ __forceinline__ unsigned long long pku(uint32_t a, uint32_t b) {
    unsigned long long r;
    asm("mov.b64 %0, {%1,%2};" : "=l"(r) : "r"(a), "r"(b));
    return r;
}
__device__ __forceinline__ unsigned long long pkf(float a, float b) {
    unsigned long long r;
    asm("mov.b64 %0, {%1,%2};" : "=l"(r) : "f"(a), "f"(b));
    return r;
}
__device__ __forceinline__ void up2(unsigned long long v, float& a, float& b) {
    asm("mov.b64 {%0,%1}, %2;" : "=f"(a), "=f"(b) : "l"(v));
}
__device__ __forceinline__ void ffma2(unsigned long long& d,
                                      unsigned long long a, unsigned long long b) {
    asm("fma.rn.f32x2 %0, %1, %2, %0;" : "+l"(d) : "l"(a), "l"(b));
}
__device__ __forceinline__ unsigned long long add2(unsigned long long a,
                                                   unsigned long long b) {
    unsigned long long r;
    asm("add.rn.f32x2 %0, %1, %2;" : "=l"(r) : "l"(a), "l"(b));
    return r;
}

extern __shared__ __align__(16) unsigned char smem[];

__global__ __launch_bounds__(NTHR, 1)
void snn_kernel(const float* __restrict__ x, const float* __restrict__ w1,
                float* __restrict__ out) {
    const int tid  = threadIdx.x;
    const int wid  = tid >> 5;
    const int lane = tid & 31;
    const int cta  = blockIdx.x;
    const int rb   = cta * M_CTA;
    const int rg   = wid >> 3;          // 2 groups of 128 rows
    const int oc   = wid & 7;           // 8 o-chunks x 8 o within 64-o quarter
    const int r0   = rg * 128 + lane;   // rows r0, r0+32, r0+64, r0+96

    // ================= layer 1: scalar fp32 IF (chain-exact) ================
    {
        float* sx  = (float*)smem;                 // [256][16]
        float* sw1 = (float*)(smem + 16384);       // [256][16]
        for (int idx = tid; idx < 256 * 16; idx += NTHR) sx[idx]  = x[rb * 16 + idx];
        for (int idx = tid; idx < 256 * 16; idx += NTHR) sw1[idx] = w1[idx];
        __syncthreads();
        const int rr = tid >> 1, h = tid & 1;
        float xr[16];
#pragma unroll
        for (int k = 0; k < 16; k++) xr[k] = sx[rr * 16 + k];
        for (int g4 = 0; g4 < 4; g4++) {
            const int wd = h * 4 + g4;
            uint32_t acc[T_STEPS];
#pragma unroll
            for (int t = 0; t < T_STEPS; t++) acc[t] = 0;
            for (int b = 0; b < 32; b++) {
                const int o = wd * 32 + b;
                float a = 0.f;
#pragma unroll
                for (int k = 0; k < 16; k++) a = fmaf(xr[k], sw1[o * 16 + k], a);
                float v = 0.f;
#pragma unroll
                for (int t = 0; t < T_STEPS; t++) {
                    v += a;
                    if (v >= 1.f) { v -= 1.f; acc[t] |= (1u << b); }
                }
            }
#pragma unroll
            for (int t = 0; t < T_STEPS; t++) g_bits[GB(0, cta, t, wd, rr)] = acc[t];
        }
        __syncthreads();
    }

    // ========== layers 2 & 3: chain-exact f32x2, R=4 rows/thread ============
    for (int L = 0; L < 2; L++) {
        const int bin = L, bout = 1 - L;
        for (int q = 0; q < 4; q++) {
            __syncthreads();
            {   // stage o-quarter weights (64KB): [256 i][64 o]
                const uint4* src = (const uint4*)&g_w23t[L][q][0][0];
                uint4* dst = (uint4*)smem;
#pragma unroll
                for (int it = 0; it < 8; it++)
                    dst[tid + it * NTHR] = src[tid + it * NTHR];
            }
            __syncthreads();

            // membrane: 4 rows x 8 o (4 pairs)
            unsigned long long vv[4][4];
#pragma unroll
            for (int j = 0; j < 4; j++)
#pragma unroll
                for (int p = 0; p < 4; p++) vv[j][p] = 0ull;

            const unsigned char* wq = smem + (size_t)oc * 32u;   // + oc*8 floats

            for (int t = 0; t < T_STEPS; t++) {
                unsigned long long acc[4][4];
#pragma unroll
                for (int j = 0; j < 4; j++)
#pragma unroll
                    for (int p = 0; p < 4; p++) acc[j][p] = 0ull;

                uint32_t W[4], Wn[4];
#pragma unroll
                for (int j = 0; j < 4; j++)
                    W[j] = g_bits[GB(bin, cta, t, 0, r0 + j * 32)];

#pragma unroll 1
                for (int w = 0; w < 8; w++) {
                    if (w < 7) {
#pragma unroll
                        for (int j = 0; j < 4; j++)
                            Wn[j] = g_bits[GB(bin, cta, t, w + 1, r0 + j * 32)];
                    }
                    const unsigned char* wb8 = wq + (size_t)(w * 32) * 256u;
#pragma unroll
                    for (int b = 0; b < 32; b++) {
                        const ulonglong2* wp = (const ulonglong2*)(wb8 + (size_t)b * 256u);
                        ulonglong2 p0 = wp[0], p1 = wp[1];
#pragma unroll
                        for (int j = 0; j < 4; j++) {
                            const uint32_t fb = ((W[j] >> b) & 1u) * 0x3F800000u;
                            const unsigned long long m = pku(fb, fb);
                            ffma2(acc[j][0], m, p0.x);
                            ffma2(acc[j][1], m, p0.y);
                            ffma2(acc[j][2], m, p1.x);
                            ffma2(acc[j][3], m, p1.y);
                        }
                    }
#pragma unroll
                    for (int j = 0; j < 4; j++) W[j] = Wn[j];
                }

                // IF: v += a (RN), spike, soft reset; publish byte per row
#pragma unroll
                for (int j = 0; j < 4; j++) {
                    uint32_t m8 = 0;
#pragma unroll
                    for (int p = 0; p < 4; p++) {
                        vv[j][p] = add2(vv[j][p], acc[j][p]);
                        float f0, f1; up2(vv[j][p], f0, f1);
                        if (f0 >= 1.f) { f0 -= 1.f; m8 |= 1u << (2 * p); }
                        if (f1 >= 1.f) { f1 -= 1.f; m8 |= 2u << (2 * p); }
                        vv[j][p] = pkf(f0, f1);
                    }
                    ((unsigned char*)g_bits)[
                        4u * GB(bout, cta, t, q * 2 + (oc >> 2), r0 + j * 32)
                        + (oc & 3)] = (unsigned char)m8;
                }
            }
        }
        __syncthreads();
    }

    // ================= layer 4: 256->16 (no thresholds after) ===============
    {
        const uint4* src = (const uint4*)&g_w4t[0][0];
        uint4* dst = (uint4*)smem;
        for (int idx = tid; idx < 1024; idx += NTHR) dst[idx] = src[idx];
    }
    __syncthreads();
    {
        for (int pass = 0; pass < 8; pass++) {
            const int item = pass * NTHR + tid;        // 4096 items = (t, r)
            const int t  = item >> 8;
            const int rr = item & 255;
            unsigned long long acc[8];
#pragma unroll
            for (int p = 0; p < 8; p++) acc[p] = 0ull;
#pragma unroll 1
            for (int w = 0; w < 8; w++) {
                const uint32_t Wb = g_bits[GB(0, cta, t, w, rr)];
                const unsigned char* wbase = smem + (size_t)(w * 32) * 64u;
#pragma unroll
                for (int b = 0; b < 32; b++) {
                    const uint32_t fb = ((Wb >> b) & 1u) * 0x3F800000u;
                    const unsigned long long m = pku(fb, fb);
                    const ulonglong2* wp = (const ulonglong2*)(wbase + (size_t)b * 64u);
                    ulonglong2 p0 = wp[0], p1 = wp[1], p2 = wp[2], p3 = wp[3];
                    ffma2(acc[0], m, p0.x); ffma2(acc[1], m, p0.y);
                    ffma2(acc[2], m, p1.x); ffma2(acc[3], m, p1.y);
                    ffma2(acc[4], m, p2.x); ffma2(acc[5], m, p2.y);
                    ffma2(acc[6], m, p3.x); ffma2(acc[7], m, p3.y);
                }
            }
            float* po = out + ((size_t)t * BATCH + rb + rr) * 16;
#pragma unroll
            for (int p = 0; p < 8; p++)
                *(unsigned long long*)(po + 2 * p) = acc[p];
        }
    }
}

extern "C" void kernel_launch(void* const* d_in, const int* in_sizes, int n_in,
                              void* d_out, int out_size) {
    const float* x  = (const float*)d_in[0];
    const float* w1 = (const float*)d_in[1];
    const float* w2 = (const float*)d_in[2];
    const float* w3 = (const float*)d_in[3];
    const float* w4 = (const float*)d_in[4];
    float* out = (float*)d_out;

    cudaFuncSetAttribute(snn_kernel, cudaFuncAttributeMaxDynamicSharedMemorySize,
                         SMEM_BYTES);
    prep_kernel<<<512, 256>>>(w2, w3, w4);
    snn_kernel<<<NBLK, NTHR, SMEM_BYTES>>>(x, w1, out);
}

// round 10
// speedup vs baseline: 1.0214x; 1.0214x over previous
#include <cuda_runtime.h>
#include <cstdint>

#define T_STEPS 16
#define BATCH   32768
#define M_CTA   256
#define NBLK    (BATCH / M_CTA)   // 128 CTAs (single wave)
#define NTHR    512               // 16 warps

#define SMEM_BYTES 65536u

// weights transposed + quartered: [L][q][i][o'] = w[(q*64+o')][i]
__device__ float g_w23t[2][4][256][64];
__device__ float g_w4t[256][16];
// spike bit planes: [buf][cta][t][wd(8)][row(256)]
__device__ uint32_t g_bits[2u * NBLK * T_STEPS * 8u * 256u];
#define GB(b,cta,t,wd,r) (((((b)*NBLK + (cta))*T_STEPS + (t))*8u + (wd))*256u + (r))

__global__ void prep_kernel(const float* __restrict__ w2, const float* __restrict__ w3,
                            const float* __restrict__ w4) {
    int idx = blockIdx.x * 256 + threadIdx.x;      // grid 512 -> 0..131071
    int L = idx >> 16;
    int o = (idx >> 8) & 255;
    int i = idx & 255;
    g_w23t[L][o >> 6][i][o & 63] = (L ? w3 : w2)[o * 256 + i];
    if (idx < 4096) {
        int ii = idx >> 4, oo = idx & 15;
        g_w4t[ii][oo] = w4[oo * 256 + ii];
    }
}

// ---- packed f32x2 helpers ----
__device__ __forceinline__ unsigned long long pku(uint32_t a, uint32_t b) {
    unsigned long long r;
    asm("mov.b64 %0, {%1,%2};" : "=l"(r) : "r"(a), "r"(b));
    return r;
}
__device__ __forceinline__ unsigned long long pkf(float a, float b) {
    unsigned long long r;
    asm("mov.b64 %0, {%1,%2};" : "=l"(r) : "f"(a), "f"(b));
    return r;
}
__device__ __forceinline__ void up2(unsigned long long v, float& a, float& b) {
    asm("mov.b64 {%0,%1}, %2;" : "=f"(a), "=f"(b) : "l"(v));
}
__device__ __forceinline__ void ffma2(unsigned long long& d,
                                      unsigned long long a, unsigned long long b) {
    asm("fma.rn.f32x2 %0, %1, %2, %0;" : "+l"(d) : "l"(a), "l"(b));
}
__device__ __forceinline__ unsigned long long add2(unsigned long long a,
                                                   unsigned long long b) {
    unsigned long long r;
    asm("add.rn.f32x2 %0, %1, %2;" : "=l"(r) : "l"(a), "l"(b));
    return r;
}
// predicated: if (bit) acc[p] += w[p] for 4 pairs — exact (fmaf(0,..) == identity)
__device__ __forceinline__ void padd4(unsigned long long& a0, unsigned long long& a1,
                                      unsigned long long& a2, unsigned long long& a3,
                                      unsigned long long w0, unsigned long long w1,
                                      unsigned long long w2, unsigned long long w3,
                                      uint32_t bit) {
    asm("{ .reg .pred p;\n\t"
        "setp.ne.u32 p, %8, 0;\n\t"
        "@p add.rn.f32x2 %0, %0, %4;\n\t"
        "@p add.rn.f32x2 %1, %1, %5;\n\t"
        "@p add.rn.f32x2 %2, %2, %6;\n\t"
        "@p add.rn.f32x2 %3, %3, %7;\n\t}"
        : "+l"(a0), "+l"(a1), "+l"(a2), "+l"(a3)
        : "l"(w0), "l"(w1), "l"(w2), "l"(w3), "r"(bit));
}

extern __shared__ __align__(16) unsigned char smem[];

__global__ __launch_bounds__(NTHR, 1)
void snn_kernel(const float* __restrict__ x, const float* __restrict__ w1,
                float* __restrict__ out) {
    const int tid  = threadIdx.x;
    const int wid  = tid >> 5;
    const int lane = tid & 31;
    const int cta  = blockIdx.x;
    const int rb   = cta * M_CTA;
    const int rg   = wid >> 3;          // 2 groups of 128 rows
    const int oc   = wid & 7;           // 8 o-chunks x 8 o within 64-o quarter
    const int r0   = rg * 128 + lane;   // rows r0, r0+32, r0+64, r0+96

    // ================= layer 1: scalar fp32 IF (chain-exact) ================
    {
        float* sx  = (float*)smem;                 // [256][16]
        float* sw1 = (float*)(smem + 16384);       // [256][16]
        for (int idx = tid; idx < 256 * 16; idx += NTHR) sx[idx]  = x[rb * 16 + idx];
        for (int idx = tid; idx < 256 * 16; idx += NTHR) sw1[idx] = w1[idx];
        __syncthreads();
        const int rr = tid >> 1, h = tid & 1;
        float xr[16];
#pragma unroll
        for (int k = 0; k < 16; k++) xr[k] = sx[rr * 16 + k];
        for (int g4 = 0; g4 < 4; g4++) {
            const int wd = h * 4 + g4;
            uint32_t acc[T_STEPS];
#pragma unroll
            for (int t = 0; t < T_STEPS; t++) acc[t] = 0;
            for (int b = 0; b < 32; b++) {
                const int o = wd * 32 + b;
                float a = 0.f;
#pragma unroll
                for (int k = 0; k < 16; k++) a = fmaf(xr[k], sw1[o * 16 + k], a);
                float v = 0.f;
#pragma unroll
                for (int t = 0; t < T_STEPS; t++) {
                    v += a;
                    if (v >= 1.f) { v -= 1.f; acc[t] |= (1u << b); }
                }
            }
#pragma unroll
            for (int t = 0; t < T_STEPS; t++) g_bits[GB(0, cta, t, wd, rr)] = acc[t];
        }
        __syncthreads();
    }

    // ===== layers 2 & 3: chain-exact predicated f32x2, R=4 rows/thread ======
    for (int L = 0; L < 2; L++) {
        const int bin = L, bout = 1 - L;
        for (int q = 0; q < 4; q++) {
            __syncthreads();
            {   // stage o-quarter weights (64KB): [256 i][64 o]
                const uint4* src = (const uint4*)&g_w23t[L][q][0][0];
                uint4* dst = (uint4*)smem;
#pragma unroll
                for (int it = 0; it < 8; it++)
                    dst[tid + it * NTHR] = src[tid + it * NTHR];
            }
            __syncthreads();

            // membrane: 4 rows x 8 o (4 pairs)
            unsigned long long vv[4][4];
#pragma unroll
            for (int j = 0; j < 4; j++)
#pragma unroll
                for (int p = 0; p < 4; p++) vv[j][p] = 0ull;

            const unsigned char* wq = smem + (size_t)oc * 32u;   // + oc*8 floats

            for (int t = 0; t < T_STEPS; t++) {
                unsigned long long acc[4][4];
#pragma unroll
                for (int j = 0; j < 4; j++)
#pragma unroll
                    for (int p = 0; p < 4; p++) acc[j][p] = 0ull;

                uint32_t W[4], Wn[4];
#pragma unroll
                for (int j = 0; j < 4; j++)
                    W[j] = g_bits[GB(bin, cta, t, 0, r0 + j * 32)];

#pragma unroll 1
                for (int w = 0; w < 8; w++) {
                    if (w < 7) {
#pragma unroll
                        for (int j = 0; j < 4; j++)
                            Wn[j] = g_bits[GB(bin, cta, t, w + 1, r0 + j * 32)];
                    }
                    const unsigned char* wb8 = wq + (size_t)(w * 32) * 256u;
#pragma unroll
                    for (int b = 0; b < 32; b++) {
                        const ulonglong2* wp = (const ulonglong2*)(wb8 + (size_t)b * 256u);
                        ulonglong2 p0 = wp[0], p1 = wp[1];
#pragma unroll
                        for (int j = 0; j < 4; j++) {
                            padd4(acc[j][0], acc[j][1], acc[j][2], acc[j][3],
                                  p0.x, p0.y, p1.x, p1.y, W[j] & (1u << b));
                        }
                    }
#pragma unroll
                    for (int j = 0; j < 4; j++) W[j] = Wn[j];
                }

                // IF: v += a (RN), spike, soft reset; publish byte per row
#pragma unroll
                for (int j = 0; j < 4; j++) {
                    uint32_t m8 = 0;
#pragma unroll
                    for (int p = 0; p < 4; p++) {
                        vv[j][p] = add2(vv[j][p], acc[j][p]);
                        float f0, f1; up2(vv[j][p], f0, f1);
                        if (f0 >= 1.f) { f0 -= 1.f; m8 |= 1u << (2 * p); }
                        if (f1 >= 1.f) { f1 -= 1.f; m8 |= 2u << (2 * p); }
                        vv[j][p] = pkf(f0, f1);
                    }
                    ((unsigned char*)g_bits)[
                        4u * GB(bout, cta, t, q * 2 + (oc >> 2), r0 + j * 32)
                        + (oc & 3)] = (unsigned char)m8;
                }
            }
        }
        __syncthreads();
    }

    // ================= layer 4: 256->16 (no thresholds after) ===============
    {
        const uint4* src = (const uint4*)&g_w4t[0][0];
        uint4* dst = (uint4*)smem;
        for (int idx = tid; idx < 1024; idx += NTHR) dst[idx] = src[idx];
    }
    __syncthreads();
    {
        for (int pass = 0; pass < 8; pass++) {
            const int item = pass * NTHR + tid;        // 4096 items = (t, r)
            const int t  = item >> 8;
            const int rr = item & 255;
            unsigned long long acc[8];
#pragma unroll
            for (int p = 0; p < 8; p++) acc[p] = 0ull;
#pragma unroll 1
            for (int w = 0; w < 8; w++) {
                const uint32_t Wb = g_bits[GB(0, cta, t, w, rr)];
                const unsigned char* wbase = smem + (size_t)(w * 32) * 64u;
#pragma unroll
                for (int b = 0; b < 32; b++) {
                    const ulonglong2* wp = (const ulonglong2*)(wbase + (size_t)b * 64u);
                    ulonglong2 p0 = wp[0], p1 = wp[1], p2 = wp[2], p3 = wp[3];
                    const uint32_t bit = Wb & (1u << b);
                    padd4(acc[0], acc[1], acc[2], acc[3], p0.x, p0.y, p1.x, p1.y, bit);
                    padd4(acc[4], acc[5], acc[6], acc[7], p2.x, p2.y, p3.x, p3.y, bit);
                }
            }
            float* po = out + ((size_t)t * BATCH + rb + rr) * 16;
#pragma unroll
            for (int p = 0; p < 8; p++)
                *(unsigned long long*)(po + 2 * p) = acc[p];
        }
    }
}

extern "C" void kernel_launch(void* const* d_in, const int* in_sizes, int n_in,
                              void* d_out, int out_size) {
    const float* x  = (const float*)d_in[0];
    const float* w1 = (const float*)d_in[1];
    const float* w2 = (const float*)d_in[2];
    const float* w3 = (const float*)d_in[3];
    const float* w4 = (const float*)d_in[4];
    float* out = (float*)d_out;

    cudaFuncSetAttribute(snn_kernel, cudaFuncAttributeMaxDynamicSharedMemorySize,
                         SMEM_BYTES);
    prep_kernel<<<512, 256>>>(w2, w3, w4);
    snn_kernel<<<NBLK, NTHR, SMEM_BYTES>>>(x, w1, out);
}

// round 11
// speedup vs baseline: 1.6184x; 1.5845x over previous
#include <cuda_runtime.h>
#include <cstdint>

#define T_STEPS 16
#define BATCH   32768
#define M_CTA   256
#define NBLK    (BATCH / M_CTA)   // 128 CTAs (single wave)
#define NTHR    512               // 16 warps

#define SMEM_BYTES 65536u

// weights transposed + quartered: [L][q][i][o'] = w[(q*64+o')][i]
__device__ float g_w23t[2][4][256][64];
__device__ float g_w4t[256][16];
// spike bit planes: [buf][cta][t][wd(8)][row(256)]
__device__ uint32_t g_bits[2u * NBLK * T_STEPS * 8u * 256u];
#define GB(b,cta,t,wd,r) (((((b)*NBLK + (cta))*T_STEPS + (t))*8u + (wd))*256u + (r))

__global__ void prep_kernel(const float* __restrict__ w2, const float* __restrict__ w3,
                            const float* __restrict__ w4) {
    int idx = blockIdx.x * 256 + threadIdx.x;      // grid 512 -> 0..131071
    int L = idx >> 16;
    int o = (idx >> 8) & 255;
    int i = idx & 255;
    g_w23t[L][o >> 6][i][o & 63] = (L ? w3 : w2)[o * 256 + i];
    if (idx < 4096) {
        int ii = idx >> 4, oo = idx & 15;
        g_w4t[ii][oo] = w4[oo * 256 + ii];
    }
}

// ---- packed f32x2 helpers ----
__device__ __forceinline__ unsigned long long pku(uint32_t a, uint32_t b) {
    unsigned long long r;
    asm("mov.b64 %0, {%1,%2};" : "=l"(r) : "r"(a), "r"(b));
    return r;
}
__device__ __forceinline__ unsigned long long pkf(float a, float b) {
    unsigned long long r;
    asm("mov.b64 %0, {%1,%2};" : "=l"(r) : "f"(a), "f"(b));
    return r;
}
__device__ __forceinline__ void up2(unsigned long long v, float& a, float& b) {
    asm("mov.b64 {%0,%1}, %2;" : "=f"(a), "=f"(b) : "l"(v));
}
__device__ __forceinline__ void ffma2(unsigned long long& d,
                                      unsigned long long a, unsigned long long b) {
    asm("fma.rn.f32x2 %0, %1, %2, %0;" : "+l"(d) : "l"(a), "l"(b));
}
__device__ __forceinline__ unsigned long long add2(unsigned long long a,
                                                   unsigned long long b) {
    unsigned long long r;
    asm("add.rn.f32x2 %0, %1, %2;" : "=l"(r) : "l"(a), "l"(b));
    return r;
}
// bit b of W -> 0x3F800000 (1.0f) or 0, via sign-extending bitfield extract (alu pipe)
__device__ __forceinline__ uint32_t bitmask(uint32_t W, int b) {
    uint32_t m;
    asm("{ .reg .s32 t;\n\t"
        "bfe.s32 t, %1, %2, 1;\n\t"
        "and.b32 %0, t, 0x3F800000;\n\t}"
        : "=r"(m) : "r"(W), "r"(b));
    return m;
}

extern __shared__ __align__(16) unsigned char smem[];

__global__ __launch_bounds__(NTHR, 1)
void snn_kernel(const float* __restrict__ x, const float* __restrict__ w1,
                float* __restrict__ out) {
    const int tid  = threadIdx.x;
    const int wid  = tid >> 5;
    const int lane = tid & 31;
    const int cta  = blockIdx.x;
    const int rb   = cta * M_CTA;
    const int rg   = wid >> 2;          // 4 groups of 64 rows
    const int oc   = wid & 3;           // 4 o-chunks x 16 o within 64-o quarter
    const int r0   = rg * 64 + lane;    // rows r0, r0+32

    // ================= layer 1: scalar fp32 IF (chain-exact) ================
    {
        float* sx  = (float*)smem;                 // [256][16]
        float* sw1 = (float*)(smem + 16384);       // [256][16]
        for (int idx = tid; idx < 256 * 16; idx += NTHR) sx[idx]  = x[rb * 16 + idx];
        for (int idx = tid; idx < 256 * 16; idx += NTHR) sw1[idx] = w1[idx];
        __syncthreads();
        const int rr = tid >> 1, h = tid & 1;
        float xr[16];
#pragma unroll
        for (int k = 0; k < 16; k++) xr[k] = sx[rr * 16 + k];
        for (int g4 = 0; g4 < 4; g4++) {
            const int wd = h * 4 + g4;
            uint32_t acc[T_STEPS];
#pragma unroll
            for (int t = 0; t < T_STEPS; t++) acc[t] = 0;
            for (int b = 0; b < 32; b++) {
                const int o = wd * 32 + b;
                float a = 0.f;
#pragma unroll
                for (int k = 0; k < 16; k++) a = fmaf(xr[k], sw1[o * 16 + k], a);
                float v = 0.f;
#pragma unroll
                for (int t = 0; t < T_STEPS; t++) {
                    v += a;
                    if (v >= 1.f) { v -= 1.f; acc[t] |= (1u << b); }
                }
            }
#pragma unroll
            for (int t = 0; t < T_STEPS; t++) g_bits[GB(0, cta, t, wd, rr)] = acc[t];
        }
        __syncthreads();
    }

    // ===== layers 2 & 3: chain-exact f32x2, R=2 rows x 16 o per thread ======
    for (int L = 0; L < 2; L++) {
        const int bin = L, bout = 1 - L;
        for (int q = 0; q < 4; q++) {
            __syncthreads();
            {   // stage o-quarter weights (64KB): [256 i][64 o]
                const uint4* src = (const uint4*)&g_w23t[L][q][0][0];
                uint4* dst = (uint4*)smem;
#pragma unroll
                for (int it = 0; it < 8; it++)
                    dst[tid + it * NTHR] = src[tid + it * NTHR];
            }
            __syncthreads();

            // membrane: 2 rows x 16 o (8 pairs)
            unsigned long long vv[2][8];
#pragma unroll
            for (int j = 0; j < 2; j++)
#pragma unroll
                for (int p = 0; p < 8; p++) vv[j][p] = 0ull;

            const unsigned char* wq = smem + (size_t)oc * 64u;   // + oc*16 floats

            for (int t = 0; t < T_STEPS; t++) {
                unsigned long long acc[2][8];
#pragma unroll
                for (int j = 0; j < 2; j++)
#pragma unroll
                    for (int p = 0; p < 8; p++) acc[j][p] = 0ull;

                uint32_t W[2], Wn[2];
#pragma unroll
                for (int j = 0; j < 2; j++)
                    W[j] = g_bits[GB(bin, cta, t, 0, r0 + j * 32)];

#pragma unroll 1
                for (int w = 0; w < 8; w++) {
                    if (w < 7) {
#pragma unroll
                        for (int j = 0; j < 2; j++)
                            Wn[j] = g_bits[GB(bin, cta, t, w + 1, r0 + j * 32)];
                    }
                    const unsigned char* wb8 = wq + (size_t)(w * 32) * 256u;
#pragma unroll
                    for (int b = 0; b < 32; b++) {
                        const ulonglong2* wp = (const ulonglong2*)(wb8 + (size_t)b * 256u);
                        ulonglong2 p0 = wp[0], p1 = wp[1], p2 = wp[2], p3 = wp[3];
#pragma unroll
                        for (int j = 0; j < 2; j++) {
                            const uint32_t m = bitmask(W[j], b);
                            const unsigned long long mm = pku(m, m);
                            ffma2(acc[j][0], mm, p0.x); ffma2(acc[j][1], mm, p0.y);
                            ffma2(acc[j][2], mm, p1.x); ffma2(acc[j][3], mm, p1.y);
                            ffma2(acc[j][4], mm, p2.x); ffma2(acc[j][5], mm, p2.y);
                            ffma2(acc[j][6], mm, p3.x); ffma2(acc[j][7], mm, p3.y);
                        }
                    }
#pragma unroll
                    for (int j = 0; j < 2; j++) W[j] = Wn[j];
                }

                // IF: v += a (RN), spike, soft reset; publish u16 per row
#pragma unroll
                for (int j = 0; j < 2; j++) {
                    uint32_t m16 = 0;
#pragma unroll
                    for (int p = 0; p < 8; p++) {
                        vv[j][p] = add2(vv[j][p], acc[j][p]);
                        float f0, f1; up2(vv[j][p], f0, f1);
                        if (f0 >= 1.f) { f0 -= 1.f; m16 |= 1u << (2 * p); }
                        if (f1 >= 1.f) { f1 -= 1.f; m16 |= 2u << (2 * p); }
                        vv[j][p] = pkf(f0, f1);
                    }
                    ((uint16_t*)g_bits)[
                        2u * GB(bout, cta, t, q * 2 + (oc >> 1), r0 + j * 32)
                        + (oc & 1)] = (uint16_t)m16;
                }
            }
        }
        __syncthreads();
    }

    // ================= layer 4: 256->16 (no thresholds after) ===============
    {
        const uint4* src = (const uint4*)&g_w4t[0][0];
        uint4* dst = (uint4*)smem;
        for (int idx = tid; idx < 1024; idx += NTHR) dst[idx] = src[idx];
    }
    __syncthreads();
    {
        for (int pass = 0; pass < 8; pass++) {
            const int item = pass * NTHR + tid;        // 4096 items = (t, r)
            const int t  = item >> 8;
            const int rr = item & 255;
            unsigned long long acc[8];
#pragma unroll
            for (int p = 0; p < 8; p++) acc[p] = 0ull;
#pragma unroll 1
            for (int w = 0; w < 8; w++) {
                const uint32_t Wb = g_bits[GB(0, cta, t, w, rr)];
                const unsigned char* wbase = smem + (size_t)(w * 32) * 64u;
#pragma unroll
                for (int b = 0; b < 32; b++) {
                    const ulonglong2* wp = (const ulonglong2*)(wbase + (size_t)b * 64u);
                    ulonglong2 p0 = wp[0], p1 = wp[1], p2 = wp[2], p3 = wp[3];
                    const uint32_t m = bitmask(Wb, b);
                    const unsigned long long mm = pku(m, m);
                    ffma2(acc[0], mm, p0.x); ffma2(acc[1], mm, p0.y);
                    ffma2(acc[2], mm, p1.x); ffma2(acc[3], mm, p1.y);
                    ffma2(acc[4], mm, p2.x); ffma2(acc[5], mm, p2.y);
                    ffma2(acc[6], mm, p3.x); ffma2(acc[7], mm, p3.y);
                }
            }
            float* po = out + ((size_t)t * BATCH + rb + rr) * 16;
#pragma unroll
            for (int p = 0; p < 8; p++)
                *(unsigned long long*)(po + 2 * p) = acc[p];
        }
    }
}

extern "C" void kernel_launch(void* const* d_in, const int* in_sizes, int n_in,
                              void* d_out, int out_size) {
    const float* x  = (const float*)d_in[0];
    const float* w1 = (const float*)d_in[1];
    const float* w2 = (const float*)d_in[2];
    const float* w3 = (const float*)d_in[3];
    const float* w4 = (const float*)d_in[4];
    float* out = (float*)d_out;

    cudaFuncSetAttribute(snn_kernel, cudaFuncAttributeMaxDynamicSharedMemorySize,
                         SMEM_BYTES);
    prep_kernel<<<512, 256>>>(w2, w3, w4);
    snn_kernel<<<NBLK, NTHR, SMEM_BYTES>>>(x, w1, out);
}